// round 4
// baseline (speedup 1.0000x reference)
#include <cuda_runtime.h>
#include <math.h>

#define BB 32
#define SS 1024
#define II 512
#define HH 512
#define GG 2048   // 4*H
#define NGRP 4    // independent batch groups
#define CPG  32   // CTAs per group
#define BPG  8    // batches per group

typedef unsigned long long u64;

// ---------------- device scratch ----------------
__device__ float g_xg[(size_t)BB * GG * SS];   // x-gates, layout [b][g][t], 256MB
__device__ float g_h[NGRP][2][BPG * HH];       // per-group h ping-pong, [b][k]
__device__ unsigned g_cnt[NGRP * 32];          // per-group barrier counter (128B apart)
__device__ unsigned g_genv[NGRP * 32];         // per-group generation

__device__ __forceinline__ unsigned ld_acq(const unsigned* p) {
    unsigned v;
    asm volatile("ld.acquire.gpu.u32 %0, [%1];" : "=r"(v) : "l"(p));
    return v;
}
__device__ __forceinline__ u64 fma2(u64 a, u64 b, u64 c) {
    u64 d;
    asm("fma.rn.f32x2 %0, %1, %2, %3;" : "=l"(d) : "l"(a), "l"(b), "l"(c));
    return d;
}
__device__ __forceinline__ u64 add2(u64 a, u64 b) {
    u64 d;
    asm("add.rn.f32x2 %0, %1, %2;" : "=l"(d) : "l"(a), "l"(b));
    return d;
}
__device__ __forceinline__ u64 pack2(float x, float y) {
    u64 r;
    asm("mov.b64 %0, {%1, %2};" : "=l"(r) : "r"(__float_as_uint(x)), "r"(__float_as_uint(y)));
    return r;
}
__device__ __forceinline__ float2 unpack2(u64 v) {
    unsigned lo, hi;
    asm("mov.b64 {%0, %1}, %2;" : "=r"(lo), "=r"(hi) : "l"(v));
    return make_float2(__uint_as_float(lo), __uint_as_float(hi));
}
// L2-only 16B load (h is rewritten every 2 steps; L1 would serve stale lines)
__device__ __forceinline__ ulonglong2 ldcg_v2u64(const void* p) {
    ulonglong2 v;
    asm volatile("ld.global.cg.v2.u64 {%0, %1}, [%2];"
                 : "=l"(v.x), "=l"(v.y) : "l"(p));
    return v;
}
__device__ __forceinline__ void stcg_f32(float* p, float v) {
    asm volatile("st.global.cg.f32 [%0], %1;" :: "l"(p), "f"(v));
}
__device__ __forceinline__ float sigmoid_fast(float x) {
    return __fdividef(1.f, 1.f + __expf(-x));
}
__device__ __forceinline__ float tanh_fast(float x) {
    float e2 = __expf(2.f * fabsf(x));
    float r  = 1.f - __fdividef(2.f, e2 + 1.f);
    return copysignf(r, x);
}

// =====================================================================
// Kernel 1: xg[b][g][t] = sum_k x[b,t,k]*W_ih[g,k] + b_ih[g] + b_hh[g]
// 128x128x16 fp32 tile, 256 thr. m-fragment strided across lanes so the
// epilogue stores float4 of consecutive t -> fully coalesced STG.128.
// =====================================================================
__global__ void __launch_bounds__(256) xgates_gemm(
    const float* __restrict__ x, const float* __restrict__ Wih,
    const float* __restrict__ bih, const float* __restrict__ bhh)
{
    __shared__ float As[16 * 132];
    __shared__ float Bs[16 * 132];

    const int tid = threadIdx.x;
    const int tx = tid & 15, ty = tid >> 4;
    const int m0 = blockIdx.y * 128;   // m = b*S + t
    const int n0 = blockIdx.x * 128;   // gate row g

    u64 acc2[4][8];  // [m-pair][j] : m-pairs (tx*4+{0,1}), (+{2,3}), (64+..), (64+..)
#pragma unroll
    for (int p = 0; p < 4; p++)
#pragma unroll
        for (int j = 0; j < 8; j++) acc2[p][j] = 0ull;

    for (int k0 = 0; k0 < II; k0 += 16) {
#pragma unroll
        for (int s = 0; s < 2; s++) {
            int li = tid + s * 256;
            int mr = li >> 2;
            int kc = (li & 3) << 2;
            float4 va = *(const float4*)&x[(size_t)(m0 + mr) * II + k0 + kc];
            As[(kc + 0) * 132 + mr] = va.x;
            As[(kc + 1) * 132 + mr] = va.y;
            As[(kc + 2) * 132 + mr] = va.z;
            As[(kc + 3) * 132 + mr] = va.w;
            float4 vb = *(const float4*)&Wih[(size_t)(n0 + mr) * II + k0 + kc];
            Bs[(kc + 0) * 132 + mr] = vb.x;
            Bs[(kc + 1) * 132 + mr] = vb.y;
            Bs[(kc + 2) * 132 + mr] = vb.z;
            Bs[(kc + 3) * 132 + mr] = vb.w;
        }
        __syncthreads();
#pragma unroll
        for (int kk = 0; kk < 16; kk++) {
            ulonglong2 a0 = *(const ulonglong2*)&As[kk * 132 + tx * 4];
            ulonglong2 a1 = *(const ulonglong2*)&As[kk * 132 + 64 + tx * 4];
            float bf[8];
            *(float4*)&bf[0] = *(const float4*)&Bs[kk * 132 + ty * 8];
            *(float4*)&bf[4] = *(const float4*)&Bs[kk * 132 + ty * 8 + 4];
#pragma unroll
            for (int j = 0; j < 8; j++) {
                u64 bb = pack2(bf[j], bf[j]);
                acc2[0][j] = fma2(a0.x, bb, acc2[0][j]);
                acc2[1][j] = fma2(a0.y, bb, acc2[1][j]);
                acc2[2][j] = fma2(a1.x, bb, acc2[2][j]);
                acc2[3][j] = fma2(a1.y, bb, acc2[3][j]);
            }
        }
        __syncthreads();
    }

    // epilogue: coalesced float4 stores along t
    const int b  = m0 >> 10;       // S = 1024, 128-row tiles never cross b
    const int t0 = m0 & 1023;
#pragma unroll
    for (int j = 0; j < 8; j++) {
        int n = n0 + ty * 8 + j;
        float bias = bih[n] + bhh[n];
#pragma unroll
        for (int i2 = 0; i2 < 2; i2++) {
            float2 lo = unpack2(acc2[i2 * 2 + 0][j]);
            float2 hi = unpack2(acc2[i2 * 2 + 1][j]);
            float4 v = make_float4(lo.x + bias, lo.y + bias, hi.x + bias, hi.y + bias);
            *(float4*)&g_xg[(size_t)b * ((size_t)GG * SS) + (size_t)n * SS
                            + t0 + i2 * 64 + tx * 4] = v;
        }
    }
}

// =====================================================================
// Kernel 2: recurrence, 4 independent groups of 32 CTAs.
// Group owns 8 batches; CTA owns 64 gate rows (16 h-idx x 4 types),
// W slice 128KB in smem, reused all 1024 steps. Per step each CTA reads
// only its group's h (16KB). Per-group barrier.
// =====================================================================
__device__ __forceinline__ void group_barrier(int gi, unsigned& my_gen) {
    unsigned old;
    asm volatile("atom.release.gpu.global.add.u32 %0, [%1], %2;"
                 : "=r"(old) : "l"(&g_cnt[gi * 32]), "r"(1u));
    if (old == (unsigned)(CPG - 1)) {
        g_cnt[gi * 32] = 0;
        asm volatile("atom.release.gpu.global.exch.b32 %0, [%1], %2;"
                     : "=r"(old) : "l"(&g_genv[gi * 32]), "r"(my_gen + 1u));
        my_gen += 1u;
    } else {
        unsigned v;
        do { v = ld_acq(&g_genv[gi * 32]); } while (v == my_gen);
        my_gen = v;
    }
}

__global__ void __launch_bounds__(256) lstm_rec(
    const float* __restrict__ Whh, const float* __restrict__ h0,
    const float* __restrict__ c0, float* __restrict__ out, int write_hc)
{
    extern __shared__ float sm[];
    float* Ws   = sm;               // 64 x 512 = 128KB
    float* part = sm + 64 * 512;    // 64 x 72  = 18KB (pitch 72 kills conflicts)

    const int tid  = threadIdx.x;
    const int w    = tid >> 5;      // warp: k chunk of 64
    const int lane = tid & 31;
    const int q    = lane & 3;      // 4-float k sub-chunk
    const int bq   = lane >> 2;     // batch within group (0..7)
    const int gi   = blockIdx.x >> 5;
    const int r    = blockIdx.x & 31;
    const int j0   = r * 16;

    // ---- W_hh slice (64 rows x 512) -> smem, once ----
#pragma unroll
    for (int s = 0; s < 32; s++) {
        int idx = tid + s * 256;          // 8192 float4 slots
        int rr  = idx >> 7;
        int k4  = (idx & 127) << 2;
        int g   = (rr >> 4) * 512 + j0 + (rr & 15);   // rr = type*16 + jj
        *(float4*)&Ws[rr * 512 + k4] = *(const float4*)&Whh[(size_t)g * HH + k4];
    }

    // ---- init c and group h buffer 0 ----
    const int j  = tid >> 3;       // reduce-phase h index (0..15), valid tid<128
    const int b  = tid & 7;        // reduce-phase batch
    const int bg = gi * BPG + b;   // global batch
    float creg = 0.f;
    if (tid < 128) {
        creg = c0[(size_t)bg * HH + j0 + j];
        g_h[gi][0][b * HH + j0 + j] = h0[(size_t)bg * HH + j0 + j];
    }

    unsigned my_gen = 0;
    if (tid == 0) my_gen = ld_acq(&g_genv[gi * 32]);
    __syncthreads();
    if (tid == 0) group_barrier(gi, my_gen);
    __syncthreads();

#pragma unroll 1
    for (int t = 0; t < SS; t++) {
        const float* hb = g_h[gi][t & 1];
        float*       hn = g_h[gi][(t + 1) & 1];

        // prefetch x-gates (L2-resident stream; off critical path)
        float xpre[4];
        if (tid < 128) {
#pragma unroll
            for (int tt = 0; tt < 4; tt++)
                xpre[tt] = __ldg(&g_xg[(size_t)bg * ((size_t)GG * SS)
                                       + (size_t)(tt * 512 + j0 + j) * SS + t]);
        }

        // ---- load this lane's 16 h values (coalesced, L2-only) ----
        u64 h2[8];
#pragma unroll
        for (int i = 0; i < 4; i++) {
            ulonglong2 v = ldcg_v2u64(&hb[bq * HH + w * 64 + i * 16 + q * 4]);
            h2[i * 2 + 0] = v.x;
            h2[i * 2 + 1] = v.y;
        }

        // ---- 64 rows x (16 k per lane) via FFMA2, q-collapse by shfl ----
#pragma unroll 8
        for (int rr = 0; rr < 64; rr++) {
            u64 aa = 0ull, bb2 = 0ull;
#pragma unroll
            for (int i = 0; i < 4; i++) {
                ulonglong2 wv = *(const ulonglong2*)&Ws[rr * 512 + w * 64 + i * 16 + q * 4];
                aa  = fma2(wv.x, h2[i * 2 + 0], aa);
                bb2 = fma2(wv.y, h2[i * 2 + 1], bb2);
            }
            float2 f = unpack2(add2(aa, bb2));
            float s = f.x + f.y;
            s += __shfl_xor_sync(0xffffffffu, s, 1);
            s += __shfl_xor_sync(0xffffffffu, s, 2);
            if (q == 0) part[rr * 72 + w * 8 + bq] = s;
        }
        __syncthreads();

        // ---- reduce across 8 warps + nonlinearity (threads 0..127) ----
        if (tid < 128) {
            float gate[4];
#pragma unroll
            for (int tt = 0; tt < 4; tt++) {
                int rr = tt * 16 + j;
                float s = xpre[tt];
#pragma unroll
                for (int ww = 0; ww < 8; ww++) s += part[rr * 72 + ww * 8 + b];
                gate[tt] = s;
            }
            float ig = sigmoid_fast(gate[0]);
            float fg = sigmoid_fast(gate[1]);
            float gg = tanh_fast(gate[2]);
            float og = sigmoid_fast(gate[3]);
            float c  = fg * creg + ig * gg;
            creg = c;
            float h  = og * tanh_fast(c);
            stcg_f32(&hn[b * HH + j0 + j], h);
            out[(size_t)bg * SS * HH + (size_t)t * HH + j0 + j] = h;
            if (t == SS - 1 && write_hc) {
                size_t base = (size_t)BB * SS * HH;
                out[base + (size_t)bg * HH + j0 + j] = h;
                out[base + (size_t)BB * HH + (size_t)bg * HH + j0 + j] = c;
            }
        }

        // ---- per-group barrier ----
        __syncthreads();
        if (tid == 0) group_barrier(gi, my_gen);
        __syncthreads();
    }
}

// =====================================================================
extern "C" void kernel_launch(void* const* d_in, const int* in_sizes, int n_in,
                              void* d_out, int out_size)
{
    const float* x   = (const float*)d_in[0];
    const float* Wih = (const float*)d_in[1];
    const float* Whh = (const float*)d_in[2];
    const float* bih = (const float*)d_in[3];
    const float* bhh = (const float*)d_in[4];
    const float* h0  = (const float*)d_in[5];
    const float* c0  = (const float*)d_in[6];
    float* out = (float*)d_out;

    long long need = (long long)BB * SS * HH + 2LL * BB * HH;
    int write_hc = ((long long)out_size >= need) ? 1 : 0;

    int smem = (64 * 512 + 64 * 72) * (int)sizeof(float);  // 128KB + 18KB
    cudaFuncSetAttribute(lstm_rec, cudaFuncAttributeMaxDynamicSharedMemorySize, smem);

    dim3 ggrid(GG / 128, (BB * SS) / 128);  // (16, 256)
    xgates_gemm<<<ggrid, 256>>>(x, Wih, bih, bhh);
    lstm_rec<<<NGRP * CPG, 256, smem>>>(Whh, h0, c0, out, write_hc);
}

// round 5
// speedup vs baseline: 1.0696x; 1.0696x over previous
#include <cuda_runtime.h>
#include <math.h>

#define BB 32
#define SS 1024
#define II 512
#define HH 512
#define GG 2048   // 4*H
#define NGRP 2    // independent batch groups
#define CPG  64   // CTAs per group
#define BPG  16   // batches per group

typedef unsigned long long u64;

// ---------------- device scratch ----------------
__device__ float g_xt[(size_t)SS * 256 * 64];   // x transposed: [t][kpair][b][2], 64MB
__device__ float g_h[NGRP][2][256 * BPG * 2];   // per-group h ping-pong: [kpair][b][2]
__device__ unsigned g_cnt[NGRP * 32];           // per-group barrier counters (128B apart)
__device__ unsigned g_genv[NGRP * 32];

__device__ __forceinline__ unsigned ld_acq(const unsigned* p) {
    unsigned v;
    asm volatile("ld.acquire.gpu.u32 %0, [%1];" : "=r"(v) : "l"(p));
    return v;
}
__device__ __forceinline__ u64 fma2(u64 a, u64 b, u64 c) {
    u64 d;
    asm("fma.rn.f32x2 %0, %1, %2, %3;" : "=l"(d) : "l"(a), "l"(b), "l"(c));
    return d;
}
__device__ __forceinline__ u64 add2(u64 a, u64 b) {
    u64 d;
    asm("add.rn.f32x2 %0, %1, %2;" : "=l"(d) : "l"(a), "l"(b));
    return d;
}
__device__ __forceinline__ float2 unpack2(u64 v) {
    unsigned lo, hi;
    asm("mov.b64 {%0, %1}, %2;" : "=r"(lo), "=r"(hi) : "l"(v));
    return make_float2(__uint_as_float(lo), __uint_as_float(hi));
}
__device__ __forceinline__ u64 ldcg_u64(const u64* p) {
    u64 v;
    asm volatile("ld.global.cg.u64 %0, [%1];" : "=l"(v) : "l"(p));
    return v;
}
__device__ __forceinline__ void stcg_f32(float* p, float v) {
    asm volatile("st.global.cg.f32 [%0], %1;" :: "l"(p), "f"(v));
}
__device__ __forceinline__ float sigmoid_fast(float x) {
    return __fdividef(1.f, 1.f + __expf(-x));
}
__device__ __forceinline__ float tanh_fast(float x) {
    float e2 = __expf(2.f * fabsf(x));
    float r  = 1.f - __fdividef(2.f, e2 + 1.f);
    return copysignf(r, x);
}

// =====================================================================
// Kernel 1 (one-time, ~40us): transpose x[b][t][k] -> g_xt[t][kp][b][2]
// =====================================================================
__global__ void __launch_bounds__(256) xpose(const float* __restrict__ x)
{
    extern __shared__ float xs[];       // 32 x 513 (pitch 513: conflict-free)
    const int t   = blockIdx.x;
    const int tid = threadIdx.x;

    // coalesced loads: 2 batch rows per pass, float4 along k
#pragma unroll
    for (int it = 0; it < 16; it++) {
        int b  = it * 2 + (tid >> 7);
        int k4 = (tid & 127) << 2;
        float4 v = *(const float4*)&x[((size_t)b * SS + t) * II + k4];
        xs[b * 513 + k4 + 0] = v.x;
        xs[b * 513 + k4 + 1] = v.y;
        xs[b * 513 + k4 + 2] = v.z;
        xs[b * 513 + k4 + 3] = v.w;
    }
    __syncthreads();

    // coalesced stores: lanes cover b for fixed kpair
#pragma unroll
    for (int it = 0; it < 32; it++) {
        int idx = tid + it * 256;       // 8192 = 256 kp x 32 b
        int kp  = idx >> 5;
        int b   = idx & 31;
        float lo = xs[b * 513 + 2 * kp];
        float hi = xs[b * 513 + 2 * kp + 1];
        *(float2*)&g_xt[((size_t)t * 256 + kp) * 64 + b * 2] = make_float2(lo, hi);
    }
}

// =====================================================================
// Kernel 2: fused persistent recurrence. 2 groups x 64 CTAs x 256 thr.
// CTA owns 32 gate rows (8 h-idx x 4 types) for its group's 16 batches.
// W_ih & W_hh slices (64KB each) resident in smem for all 1024 steps.
// Per step: phase A = x_t @ W_ih^T, phase B = h @ W_hh^T (h latency
// hidden behind phase A), reduce + nonlinearity, per-group barrier.
// =====================================================================
__device__ __forceinline__ void group_barrier(int gi, unsigned& my_gen) {
    unsigned old;
    asm volatile("atom.release.gpu.global.add.u32 %0, [%1], %2;"
                 : "=r"(old) : "l"(&g_cnt[gi * 32]), "r"(1u));
    if (old == (unsigned)(CPG - 1)) {
        g_cnt[gi * 32] = 0;
        asm volatile("atom.release.gpu.global.exch.b32 %0, [%1], %2;"
                     : "=r"(old) : "l"(&g_genv[gi * 32]), "r"(my_gen + 1u));
        my_gen += 1u;
    } else {
        unsigned v;
        do { v = ld_acq(&g_genv[gi * 32]); } while (v == my_gen);
        my_gen = v;
    }
}

// one FMA phase: 32 rows x (this lane's 16 k-pairs) -> part[row][w][b]
__device__ __forceinline__ void fma_phase(
    const float* __restrict__ Wsm, const u64* __restrict__ v2,
    float* __restrict__ part, int kbase, int w, int ks, int b)
{
#pragma unroll 4
    for (int rr = 0; rr < 32; rr++) {
        u64 a0 = 0ull, a1 = 0ull;
#pragma unroll
        for (int i = 0; i < 8; i++) {
            ulonglong2 wv = *(const ulonglong2*)&Wsm[rr * 512 + kbase + i * 4];
            a0 = fma2(wv.x, v2[2 * i + 0], a0);
            a1 = fma2(wv.y, v2[2 * i + 1], a1);
        }
        float2 f = unpack2(add2(a0, a1));
        float s = f.x + f.y;
        s += __shfl_xor_sync(0xffffffffu, s, 16);
        if (ks == 0) part[rr * 136 + w * 16 + b] = s;
    }
}

__global__ void __launch_bounds__(256) lstm_rec(
    const float* __restrict__ Wih, const float* __restrict__ Whh,
    const float* __restrict__ bih, const float* __restrict__ bhh,
    const float* __restrict__ h0, const float* __restrict__ c0,
    float* __restrict__ out, int write_hc)
{
    extern __shared__ float sm[];
    float* Wih_s  = sm;                       // 32 x 512 = 64KB
    float* Whh_s  = sm + 32 * 512;            // 64KB
    float* part_x = sm + 64 * 512;            // 32 x 136 = 17408B
    float* part_h = part_x + 32 * 136;

    const int tid  = threadIdx.x;
    const int w    = tid >> 5;          // warp: 64-k chunk
    const int lane = tid & 31;
    const int ks   = lane >> 4;         // k half within chunk
    const int b    = lane & 15;         // batch within group
    const int gi   = blockIdx.x >> 6;   // group
    const int r    = blockIdx.x & 63;
    const int j0   = r * 8;             // h-index base
    const int kbase = w * 64 + ks * 32; // float offset of lane's 32 k's

    // ---- load W_ih and W_hh slices (32 rows x 512 each) ----
#pragma unroll
    for (int s = 0; s < 16; s++) {
        int idx = tid + s * 256;            // 4096 float4 slots
        int rr  = idx >> 7;
        int k4  = (idx & 127) << 2;
        int g   = (rr >> 3) * 512 + j0 + (rr & 7);
        *(float4*)&Wih_s[rr * 512 + k4] = *(const float4*)&Wih[(size_t)g * II + k4];
        *(float4*)&Whh_s[rr * 512 + k4] = *(const float4*)&Whh[(size_t)g * HH + k4];
    }

    // ---- reduce-thread state: (j, bb) for tid < 128 ----
    const int j  = tid >> 4;            // 0..7
    const int bb = tid & 15;            // batch within group
    const int bg = gi * BPG + bb;       // global batch
    float creg = 0.f;
    float breg[4];
    if (tid < 128) {
        creg = c0[(size_t)bg * HH + j0 + j];
        // scatter h0 into group buffer [kpair][b][2]
        int hj = j0 + j;
        g_h[gi][0][(hj >> 1) * 32 + bb * 2 + (hj & 1)] = h0[(size_t)bg * HH + hj];
#pragma unroll
        for (int tt = 0; tt < 4; tt++) {
            int g = tt * 512 + j0 + j;
            breg[tt] = bih[g] + bhh[g];
        }
    }

    unsigned my_gen = 0;
    if (tid == 0) my_gen = ld_acq(&g_genv[gi * 32]);
    __syncthreads();
    if (tid == 0) group_barrier(gi, my_gen);
    __syncthreads();

    const u64* xt64 = (const u64*)g_xt;

#pragma unroll 1
    for (int t = 0; t < SS; t++) {
        const u64* hb = (const u64*)g_h[gi][t & 1];
        float*     hn = g_h[gi][(t + 1) & 1];

        // issue h loads first (longest latency: freshly written to L2)
        u64 h2[16];
#pragma unroll
        for (int i = 0; i < 16; i++)
            h2[i] = ldcg_u64(&hb[(w * 32 + ks * 16 + i) * 16 + b]);

        // x loads (streaming, L2/DRAM friendly)
        u64 x2[16];
#pragma unroll
        for (int i = 0; i < 16; i++)
            x2[i] = ldcg_u64(&xt64[((size_t)t * 256 + w * 32 + ks * 16 + i) * 32
                                   + gi * BPG + b]);

        // phase A: x contribution (covers h load latency)
        fma_phase(Wih_s, x2, part_x, kbase, w, ks, b);
        // phase B: h contribution
        fma_phase(Whh_s, h2, part_h, kbase, w, ks, b);
        __syncthreads();

        // reduce + nonlinearity (threads 0..127)
        if (tid < 128) {
            float gate[4];
#pragma unroll
            for (int tt = 0; tt < 4; tt++) {
                int rr = tt * 8 + j;
                float s = breg[tt];
#pragma unroll
                for (int ww = 0; ww < 8; ww++)
                    s += part_x[rr * 136 + ww * 16 + bb]
                       + part_h[rr * 136 + ww * 16 + bb];
                gate[tt] = s;
            }
            float ig = sigmoid_fast(gate[0]);
            float fg = sigmoid_fast(gate[1]);
            float gg = tanh_fast(gate[2]);
            float og = sigmoid_fast(gate[3]);
            float c  = fg * creg + ig * gg;
            creg = c;
            float h  = og * tanh_fast(c);
            int hj = j0 + j;
            stcg_f32(&hn[(hj >> 1) * 32 + bb * 2 + (hj & 1)], h);
            out[((size_t)bg * SS + t) * HH + hj] = h;
            if (t == SS - 1 && write_hc) {
                size_t base = (size_t)BB * SS * HH;
                out[base + (size_t)bg * HH + hj] = h;
                out[base + (size_t)BB * HH + (size_t)bg * HH + hj] = c;
            }
        }

        __syncthreads();
        if (tid == 0) group_barrier(gi, my_gen);
        __syncthreads();
    }
}

// =====================================================================
extern "C" void kernel_launch(void* const* d_in, const int* in_sizes, int n_in,
                              void* d_out, int out_size)
{
    const float* x   = (const float*)d_in[0];
    const float* Wih = (const float*)d_in[1];
    const float* Whh = (const float*)d_in[2];
    const float* bih = (const float*)d_in[3];
    const float* bhh = (const float*)d_in[4];
    const float* h0  = (const float*)d_in[5];
    const float* c0  = (const float*)d_in[6];
    float* out = (float*)d_out;

    long long need = (long long)BB * SS * HH + 2LL * BB * HH;
    int write_hc = ((long long)out_size >= need) ? 1 : 0;

    int xpose_smem = 32 * 513 * (int)sizeof(float);                 // ~64KB
    int rec_smem   = (64 * 512 + 2 * 32 * 136) * (int)sizeof(float); // ~148KB
    cudaFuncSetAttribute(xpose, cudaFuncAttributeMaxDynamicSharedMemorySize, xpose_smem);
    cudaFuncSetAttribute(lstm_rec, cudaFuncAttributeMaxDynamicSharedMemorySize, rec_smem);

    xpose<<<SS, 256, xpose_smem>>>(x);
    lstm_rec<<<NGRP * CPG, 256, rec_smem>>>(Wih, Whh, bih, bhh, h0, c0, out, write_hc);
}

// round 6
// speedup vs baseline: 1.3413x; 1.2540x over previous
#include <cuda_runtime.h>
#include <math.h>

#define BB 32
#define SS 1024
#define II 512
#define HH 512
#define GG 2048   // 4*H

typedef unsigned long long u64;

// ---------------- device scratch ----------------
__device__ float g_xt[(size_t)SS * 256 * 64];   // x transposed: [t][kpair][b][2], 64MB
__device__ float g_hb[2][HH * BB];              // h ping-pong: [kpair][b][2]
__device__ unsigned g_sub[8 * 32];              // hierarchical barrier: 8 sub-counters
__device__ unsigned g_top[32];
__device__ unsigned g_gen;                      // gen == w  <=>  arrival window w-1 done

__device__ __forceinline__ unsigned ld_acq(const unsigned* p) {
    unsigned v;
    asm volatile("ld.acquire.gpu.u32 %0, [%1];" : "=r"(v) : "l"(p));
    return v;
}
__device__ __forceinline__ u64 fma2(u64 a, u64 b, u64 c) {
    u64 d;
    asm("fma.rn.f32x2 %0, %1, %2, %3;" : "=l"(d) : "l"(a), "l"(b), "l"(c));
    return d;
}
__device__ __forceinline__ u64 add2(u64 a, u64 b) {
    u64 d;
    asm("add.rn.f32x2 %0, %1, %2;" : "=l"(d) : "l"(a), "l"(b));
    return d;
}
__device__ __forceinline__ u64 pack2(float x, float y) {
    u64 r;
    asm("mov.b64 %0, {%1, %2};" : "=l"(r) : "r"(__float_as_uint(x)), "r"(__float_as_uint(y)));
    return r;
}
__device__ __forceinline__ float2 unpack2(u64 v) {
    unsigned lo, hi;
    asm("mov.b64 {%0, %1}, %2;" : "=r"(lo), "=r"(hi) : "l"(v));
    return make_float2(__uint_as_float(lo), __uint_as_float(hi));
}
__device__ __forceinline__ u64 ldcg_u64(const u64* p) {
    u64 v;
    asm volatile("ld.global.cg.u64 %0, [%1];" : "=l"(v) : "l"(p));
    return v;
}
__device__ __forceinline__ void stcg_u64(u64* p, u64 v) {
    asm volatile("st.global.cg.u64 [%0], %1;" :: "l"(p), "l"(v));
}
__device__ __forceinline__ float sigmoid_fast(float x) {
    return __fdividef(1.f, 1.f + __expf(-x));
}
__device__ __forceinline__ float tanh_fast(float x) {
    float e2 = __expf(2.f * fabsf(x));
    float r  = 1.f - __fdividef(2.f, e2 + 1.f);
    return copysignf(r, x);
}

// =====================================================================
// Kernel 1 (one-time ~30us): x[b][t][k] -> g_xt[t][kpair][b][2]
// =====================================================================
__global__ void __launch_bounds__(256) xpose(const float* __restrict__ x)
{
    extern __shared__ float xs[];   // 32 x 513
    const int t   = blockIdx.x;
    const int tid = threadIdx.x;
#pragma unroll
    for (int it = 0; it < 16; it++) {
        int b  = it * 2 + (tid >> 7);
        int k4 = (tid & 127) << 2;
        float4 v = *(const float4*)&x[((size_t)b * SS + t) * II + k4];
        xs[b * 513 + k4 + 0] = v.x;
        xs[b * 513 + k4 + 1] = v.y;
        xs[b * 513 + k4 + 2] = v.z;
        xs[b * 513 + k4 + 3] = v.w;
    }
    __syncthreads();
#pragma unroll
    for (int it = 0; it < 32; it++) {
        int idx = tid + it * 256;      // 8192 = 256 kp x 32 b
        int kp  = idx >> 5;
        int b   = idx & 31;
        float lo = xs[b * 513 + 2 * kp];
        float hi = xs[b * 513 + 2 * kp + 1];
        *(float2*)&g_xt[((size_t)t * 256 + kp) * 64 + b * 2] = make_float2(lo, hi);
    }
}

// =====================================================================
// hierarchical barrier arrive (tid 0 only). Monotonic windows; window SS
// performs the cleanup reset so graph replays start from zero state.
// =====================================================================
__device__ __forceinline__ void arrive(unsigned win, int ctaid)
{
    unsigned old;
    int s = ctaid & 7;
    asm volatile("atom.acq_rel.gpu.global.add.u32 %0, [%1], %2;"
                 : "=r"(old) : "l"(&g_sub[s * 32]), "r"(1u));
    if (old == win * 16u + 15u) {
        asm volatile("atom.acq_rel.gpu.global.add.u32 %0, [%1], %2;"
                     : "=r"(old) : "l"(&g_top[0]), "r"(1u));
        if (old == win * 8u + 7u) {
            if (win == (unsigned)SS) {
                // final window: reset all state for the next launch/replay
#pragma unroll
                for (int i = 0; i < 8; i++) g_sub[i * 32] = 0;
                g_top[0] = 0;
                asm volatile("atom.release.gpu.global.exch.b32 %0, [%1], %2;"
                             : "=r"(old) : "l"(&g_gen), "r"(0u));
            } else {
                asm volatile("atom.release.gpu.global.exch.b32 %0, [%1], %2;"
                             : "=r"(old) : "l"(&g_gen), "r"(win + 1u));
            }
        }
    }
}

// one FMA phase: 16 rows x this warp's 64-k chunk, warp-uniform W (1 wf/LDS)
__device__ __forceinline__ void fma_phase(
    const float* __restrict__ Wp, const u64* __restrict__ v2,
    float* __restrict__ sums, int kb)
{
#pragma unroll
    for (int r0 = 0; r0 < 16; r0 += 4) {
        u64 a0[4], a1[4];
#pragma unroll
        for (int rr = 0; rr < 4; rr++) { a0[rr] = 0ull; a1[rr] = 0ull; }
#pragma unroll
        for (int q = 0; q < 16; q++) {
#pragma unroll
            for (int rr = 0; rr < 4; rr++) {
                ulonglong2 wv = *(const ulonglong2*)&Wp[(r0 + rr) * 512 + kb + q * 4];
                a0[rr] = fma2(wv.x, v2[2 * q + 0], a0[rr]);
                a1[rr] = fma2(wv.y, v2[2 * q + 1], a1[rr]);
            }
        }
#pragma unroll
        for (int rr = 0; rr < 4; rr++) {
            float2 f = unpack2(add2(a0[rr], a1[rr]));
            sums[r0 + rr] += f.x + f.y;
        }
    }
}

// =====================================================================
// Kernel 2: fused persistent LSTM. 128 CTAs x 256 thr. CTA owns 4 h-idx
// (16 gate rows). W_ih + W_hh slices in smem (64KB). lane = batch.
// Per step: x-FMA (hides barrier) -> gen-wait -> h-load + x(t+1) prefetch
// -> h-FMA -> STS -> sync -> warp0 reduce/nonlin/store + arrive.
// =====================================================================
__global__ void __launch_bounds__(256, 1) lstm_rec(
    const float* __restrict__ Wih, const float* __restrict__ Whh,
    const float* __restrict__ bih, const float* __restrict__ bhh,
    const float* __restrict__ h0, const float* __restrict__ c0,
    float* __restrict__ out, int write_hc)
{
    extern __shared__ float sm[];
    float* Wih_s = sm;                 // 16 x 512
    float* Whh_s = sm + 16 * 512;      // 16 x 512
    float* part  = sm + 32 * 512;      // [16 rows][8 w][32 b] = 16KB

    const int tid  = threadIdx.x;
    const int w    = tid >> 5;
    const int lane = tid & 31;         // lane = batch
    const int cta  = blockIdx.x;
    const int j0   = cta * 4;          // 4 h-indices per CTA
    const int kb   = w * 64;           // this warp's k chunk (floats)

    // ---- load W slices (16 rows x 512 each), rows ordered r = type*4 + j ----
#pragma unroll
    for (int s = 0; s < 16; s++) {
        int idx = tid + s * 256;              // 4096 float4 slots
        int mat = idx >> 11;                  // 0 = Wih, 1 = Whh
        int rr  = (idx & 2047) >> 7;
        int k4  = (idx & 127) << 2;
        int g   = (rr >> 2) * 512 + j0 + (rr & 3);
        float* dst = (mat ? Whh_s : Wih_s) + rr * 512 + k4;
        const float* src = (mat ? Whh : Wih) + (size_t)g * 512 + k4;
        *(float4*)dst = *(const float4*)src;
    }

    // ---- warp 0 state: lane = batch b; holds c and biases for j0..j0+3 ----
    float4 creg = make_float4(0.f, 0.f, 0.f, 0.f);
    float4 bias[4];
    u64* hb64_0 = (u64*)g_hb[0];
    if (w == 0) {
        creg = *(const float4*)&c0[(size_t)lane * HH + j0];
        float4 hv = *(const float4*)&h0[(size_t)lane * HH + j0];
        stcg_u64(&hb64_0[(j0 >> 1) * 32 + lane],     pack2(hv.x, hv.y));
        stcg_u64(&hb64_0[((j0 >> 1) + 1) * 32 + lane], pack2(hv.z, hv.w));
#pragma unroll
        for (int t4 = 0; t4 < 4; t4++) {
            float4 b1 = *(const float4*)&bih[t4 * 512 + j0];
            float4 b2 = *(const float4*)&bhh[t4 * 512 + j0];
            bias[t4] = make_float4(b1.x + b2.x, b1.y + b2.y, b1.z + b2.z, b1.w + b2.w);
        }
    }
    __syncthreads();
    if (tid == 0) arrive(0u, cta);     // window 0: h0 published

    const u64* xt64 = (const u64*)g_xt;

    // preload x for t = 0
    u64 x2[32];
#pragma unroll
    for (int i = 0; i < 32; i++)
        x2[i] = ldcg_u64(&xt64[((size_t)0 * 256 + w * 32 + i) * 32 + lane]);

#pragma unroll 1
    for (int t = 0; t < SS; t++) {
        float sums[16];
#pragma unroll
        for (int r = 0; r < 16; r++) sums[r] = 0.f;

        // ---- phase A: x contribution (no dependency -> hides barrier wait) ----
        fma_phase(Wih_s, x2, sums, kb);

        // ---- wait: h for step t published (window t complete) ----
        while (ld_acq(&g_gen) < (unsigned)(t + 1)) { }

        // ---- h loads (L2, fresh), then x prefetch for t+1 ----
        const u64* hb64 = (const u64*)g_hb[t & 1];
        u64 h2[32];
#pragma unroll
        for (int i = 0; i < 32; i++)
            h2[i] = ldcg_u64(&hb64[(w * 32 + i) * 32 + lane]);
        int tn = (t + 1 < SS) ? (t + 1) : t;
#pragma unroll
        for (int i = 0; i < 32; i++)
            x2[i] = ldcg_u64(&xt64[((size_t)tn * 256 + w * 32 + i) * 32 + lane]);

        // ---- phase B: h contribution into the same sums ----
        fma_phase(Whh_s, h2, sums, kb);

#pragma unroll
        for (int r = 0; r < 16; r++)
            part[r * 256 + w * 32 + lane] = sums[r];
        __syncthreads();

        // ---- warp 0: reduce + nonlinearity + stores + arrive ----
        if (w == 0) {
            float gate[4][4];   // [type][j]
#pragma unroll
            for (int t4 = 0; t4 < 4; t4++) {
                float bv[4] = {bias[t4].x, bias[t4].y, bias[t4].z, bias[t4].w};
#pragma unroll
                for (int j = 0; j < 4; j++) {
                    int r = t4 * 4 + j;
                    float s = bv[j];
#pragma unroll
                    for (int ww = 0; ww < 8; ww++)
                        s += part[r * 256 + ww * 32 + lane];
                    gate[t4][j] = s;
                }
            }
            float hv[4], cv[4];
            float cr[4] = {creg.x, creg.y, creg.z, creg.w};
#pragma unroll
            for (int j = 0; j < 4; j++) {
                float ig = sigmoid_fast(gate[0][j]);
                float fg = sigmoid_fast(gate[1][j]);
                float gg = tanh_fast(gate[2][j]);
                float og = sigmoid_fast(gate[3][j]);
                float c  = fg * cr[j] + ig * gg;
                cv[j] = c;
                hv[j] = og * tanh_fast(c);
            }
            creg = make_float4(cv[0], cv[1], cv[2], cv[3]);

            u64* hn64 = (u64*)g_hb[(t + 1) & 1];
            stcg_u64(&hn64[(j0 >> 1) * 32 + lane],       pack2(hv[0], hv[1]));
            stcg_u64(&hn64[((j0 >> 1) + 1) * 32 + lane], pack2(hv[2], hv[3]));
            *(float4*)&out[((size_t)lane * SS + t) * HH + j0] =
                make_float4(hv[0], hv[1], hv[2], hv[3]);
            if (t == SS - 1 && write_hc) {
                size_t base = (size_t)BB * SS * HH;
                *(float4*)&out[base + (size_t)lane * HH + j0] =
                    make_float4(hv[0], hv[1], hv[2], hv[3]);
                *(float4*)&out[base + (size_t)BB * HH + (size_t)lane * HH + j0] =
                    make_float4(cv[0], cv[1], cv[2], cv[3]);
            }
            __syncwarp();
            if (lane == 0) arrive((unsigned)(t + 1), cta);
        }
        // NO trailing syncthreads: warps 1-7 run ahead into step t+1 phase A.
        // part overwrite at t+1 is gated by the gen-wait (needs our arrive).
    }
}

// =====================================================================
extern "C" void kernel_launch(void* const* d_in, const int* in_sizes, int n_in,
                              void* d_out, int out_size)
{
    const float* x   = (const float*)d_in[0];
    const float* Wih = (const float*)d_in[1];
    const float* Whh = (const float*)d_in[2];
    const float* bih = (const float*)d_in[3];
    const float* bhh = (const float*)d_in[4];
    const float* h0  = (const float*)d_in[5];
    const float* c0  = (const float*)d_in[6];
    float* out = (float*)d_out;

    long long need = (long long)BB * SS * HH + 2LL * BB * HH;
    int write_hc = ((long long)out_size >= need) ? 1 : 0;

    int xpose_smem = 32 * 513 * (int)sizeof(float);                  // ~64KB
    int rec_smem   = (32 * 512 + 16 * 256) * (int)sizeof(float);     // 80KB
    cudaFuncSetAttribute(xpose, cudaFuncAttributeMaxDynamicSharedMemorySize, xpose_smem);
    cudaFuncSetAttribute(lstm_rec, cudaFuncAttributeMaxDynamicSharedMemorySize, rec_smem);

    xpose<<<SS, 256, xpose_smem>>>(x);
    lstm_rec<<<128, 256, rec_smem>>>(Wih, Whh, bih, bhh, h0, c0, out, write_hc);
}